// round 16
// baseline (speedup 1.0000x reference)
#include <cuda_runtime.h>
#include <cuda_fp16.h>
#include <math.h>
#include <stdint.h>

// ---------------- problem constants ----------------
#define NB 32
#define NS 2048
#define NE 300
#define NH 256
#define NT 24
#define NROWS 65536            // NB*NS
#define XN 1024                 // x-gates per row: j*4 + {i,o,u,f}
#define HCNT 16777216           // NROWS*NH

// ---------------- step-GEMM tiling ----------------
#define BM 128                  // rows per CTA
#define NTL 8                   // 1280 / 160 n-tiles
#define UB_NT_STRIDE 40960      // fp16 elems per 80-col packed tile (8 kchunks)
#define UB_TOTAL (16 * UB_NT_STRIDE)
#define WP_TOTAL (20 * 16384)   // W pack: 20 kcs * 1024 cols * 16

// ---------------- k_step dynamic smem (bytes) ------
// occupancy-2 layout: 86016 B/CTA -> 2 CTAs/SM (172 KB of 228 KB)
#define OFF_IDX   0             // sL/sR/sD/sRow: 4 * 512
#define OFF_A0    2048          // 3 x (128 x 64 fp16 = 16384)
#define OFF_A1    18432
#define OFF_A2    34816
#define OFF_STAGE 2048          // 128 x 164 f32 = 83968 (reuses A bufs)
#define SMEM_DYN  86016

// ---------------- device scratch -------------------
__device__ __half g_x[(size_t)NROWS * XN];    // 128 MiB packed x-gates (fp16)
__device__ __half g_Wp[WP_TOTAL];             // W fragment-native fp16 hi
__device__ float g_bias[XN];
__device__ __half g_UBH[UB_TOTAL];            // U fragment-native fp16 hi
__device__ __half g_hh[2 * (size_t)HCNT];     // h hi, 2 alternation buffers
__device__ __half g_hl[2 * (size_t)HCNT];     // h lo
__device__ float g_c[2 * (size_t)HCNT];       // c fp32
__device__ int      g_win[NT * NROWS];        // per-step winner s for each (b,d)
__device__ uint32_t g_wmask[NROWS];           // bit t: row won at step t
__device__ int      g_work[NT * NROWS];       // per-step compacted winner lists
__device__ int4     g_meta[NT * NROWS];       // per-step {offL, offR, offD, row}
__device__ int      g_cnt[NT];

__device__ __forceinline__ float sigm(float x) { return 1.0f / (1.0f + __expf(-x)); }

__device__ __forceinline__ uint32_t smem_u32(const void* p) {
    uint32_t r;
    asm("{ .reg .u64 t; cvta.to.shared.u64 t, %1; cvt.u32.u64 %0, t; }" : "=r"(r) : "l"(p));
    return r;
}
__device__ __forceinline__ void ldsm4(uint32_t* r, uint32_t addr) {
    asm volatile("ldmatrix.sync.aligned.m8n8.x4.shared.b16 {%0,%1,%2,%3}, [%4];"
                 : "=r"(r[0]), "=r"(r[1]), "=r"(r[2]), "=r"(r[3]) : "r"(addr));
}
#define MMA(d, a, bx, by) asm volatile( \
    "mma.sync.aligned.m16n8k16.row.col.f32.f16.f16.f32 " \
    "{%0,%1,%2,%3},{%4,%5,%6,%7},{%8,%9},{%0,%1,%2,%3};" \
    : "+f"((d)[0]), "+f"((d)[1]), "+f"((d)[2]), "+f"((d)[3]) \
    : "r"((a)[0]), "r"((a)[1]), "r"((a)[2]), "r"((a)[3]), "r"(bx), "r"(by))

__device__ __forceinline__ void cp16(uint32_t dst, const void* src) {
    asm volatile("{\n\t.reg .u64 g;\n\tcvta.to.global.u64 g, %1;\n\t"
                 "cp.async.cg.shared.global [%0], [g], 16;\n\t}"
                 :: "r"(dst), "l"(src) : "memory");
}
#define CP_COMMIT asm volatile("cp.async.commit_group;" ::: "memory")
#define CP_WAIT1  asm volatile("cp.async.wait_group 1;" ::: "memory")
#define CP_WAIT0  asm volatile("cp.async.wait_group 0;" ::: "memory")

__device__ __forceinline__ uint32_t packh2(float a, float b) {
    __half2 v = __floats2half2_rn(a, b);
    return *(uint32_t*)&v;
}

// ---------------- init: zero ONLY buffer 1 of state (buf0 always written
// before first read: readers with n prior writes read buf[(n+1)&1]) ----------
__global__ void k_init() {
    size_t i = (size_t)blockIdx.x * blockDim.x + threadIdx.x;
    size_t stride = (size_t)gridDim.x * blockDim.x;
    uint32_t* ph = (uint32_t*)g_hh;   // u32 p covers halves 2p,2p+1
    uint32_t* pl = (uint32_t*)g_hl;
    for (size_t p = (size_t)(HCNT / 2) + i; p < (size_t)HCNT; p += stride) {
        ph[p] = 0u; pl[p] = 0u;
    }
    for (size_t p = (size_t)HCNT + i; p < 2 * (size_t)HCNT; p += stride) g_c[p] = 0.0f;
    for (size_t p = i; p < (size_t)(NT * NROWS); p += stride) g_win[p] = -1;
    for (size_t p = i; p < (size_t)NROWS; p += stride) g_wmask[p] = 0u;
    if (i < NT) g_cnt[i] = 0;
}

// ---- pack W: fragment-native fp16 hi; also bias ----
__global__ void k_pack_wp(const float* __restrict__ W_iou, const float* __restrict__ b_iou,
                          const float* __restrict__ W_f,   const float* __restrict__ b_f) {
    int idx = blockIdx.x * blockDim.x + threadIdx.x;
    if (idx < WP_TOTAL) {
        int kcs = idx >> 14;
        int rem = idx & 16383;
        int ncol = rem >> 4, low = rem & 15;
        int c = low >> 2, e = low & 3;
        int kin = (e < 2) ? (2 * c + e) : (8 + 2 * c + (e - 2));
        int k = (kcs >> 2) * 64 + (kcs & 3) * 16 + kin;
        int j = ncol >> 2, g = ncol & 3;
        float v = 0.0f;
        if (k < NE) v = (g < 3) ? W_iou[k * 768 + g * 256 + j] : W_f[k * 256 + j];
        g_Wp[idx] = __float2half_rn(v);
    }
    if (idx < XN) {
        int j = idx >> 2, g = idx & 3;
        g_bias[idx] = (g < 3) ? b_iou[g * 256 + j] : b_f[j];
    }
}

// ---- pack U: fragment-native fp16 hi (16 tiles of 80 cols) ----
__global__ void k_pack_ub(const float* __restrict__ Ul, const float* __restrict__ Ur,
                          const float* __restrict__ Fll, const float* __restrict__ Flr,
                          const float* __restrict__ Frl, const float* __restrict__ Frr) {
    int idx = blockIdx.x * blockDim.x + threadIdx.x;
    if (idx >= UB_TOTAL) return;
    int e = idx & 3, c = (idx >> 2) & 3;
    int n = (idx >> 4) % 80;
    int q = (idx >> 4) / 80;           // ntl*32 + kc*4 + s
    int s = q & 3, kc = (q >> 2) & 7, ntl = q >> 5;
    int kin = (e < 2) ? (2 * c + e) : (8 + 2 * c + (e - 2));
    int k = kc * 64 + s * 16 + kin;
    int ncol = ntl * 80 + n;
    int j = ncol / 5, g = ncol - 5 * j;
    float v;
    if (k < 256) {
        v = (g == 0) ? Ul[k * 768 + j]
          : (g == 1) ? Ul[k * 768 + 256 + j]
          : (g == 2) ? Ul[k * 768 + 512 + j]
          : (g == 3) ? Fll[k * 256 + j]
                     : Frl[k * 256 + j];
    } else {
        int kr = k - 256;
        v = (g == 0) ? Ur[kr * 768 + j]
          : (g == 1) ? Ur[kr * 768 + 256 + j]
          : (g == 2) ? Ur[kr * 768 + 512 + j]
          : (g == 3) ? Flr[kr * 256 + j]
                     : Frr[kr * 256 + j];
    }
    g_UBH[idx] = __float2half_rn(v);
}

// ---------------- tensorized x-projection: g_x = fp16(X @ W + b) ----------------
// single-pass A-hi (x already stored fp16; A-lo pass below x-storage noise)
__global__ __launch_bounds__(512, 1) void k_xgemm_mma(const float* __restrict__ X) {
    __shared__ __align__(16) char xs[16384];   // AH only
    int mt = blockIdx.x, nt = blockIdx.y;
    int tid = threadIdx.x;
    int warp = tid >> 5, lane = tid & 31;
    int warpM = warp & 3, warpN = warp >> 2;
    uint32_t sb = smem_u32(xs);

    int arow = tid >> 2, aq = tid & 3;
    int b0 = arow * 128 + aq * 32;
    int s0 = b0 ^ ((b0 >> 3) & 0x70);
    int s1 = (b0 + 16) ^ (((b0 + 16) >> 3) & 0x70);
    const float* xrow = X + (size_t)(mt * 128 + arow) * NE;

    float acc[2][8][4];
#pragma unroll
    for (int m = 0; m < 2; m++)
#pragma unroll
        for (int f = 0; f < 8; f++)
#pragma unroll
            for (int i = 0; i < 4; i++) acc[m][f][i] = 0.0f;

    int r0 = warpM * 32 + (lane & 15);
    int r1 = r0 + 16;
    int segb = ((lane >> 4) & 1) * 16;
    int lanepart = (lane >> 2) * 16 + (lane & 3) * 4;
    int nbase = (nt * 256 + warpN * 64) * 16 + lanepart;

    float v[16];
    {
        int k0 = aq * 16;
#pragma unroll
        for (int i = 0; i < 4; i++) *(float4*)&v[i * 4] = *(const float4*)(xrow + k0 + i * 4);
    }

    for (int kc = 0; kc < 5; kc++) {
        __syncthreads();
        {
            uint4 ph;
            uint32_t* hp = (uint32_t*)&ph;
#pragma unroll
            for (int p = 0; p < 4; p++) hp[p] = packh2(v[2 * p], v[2 * p + 1]);
            *(uint4*)(xs + s0) = ph;
#pragma unroll
            for (int p = 0; p < 4; p++) hp[p] = packh2(v[8 + 2 * p], v[8 + 2 * p + 1]);
            *(uint4*)(xs + s1) = ph;
        }
        __syncthreads();
        if (kc < 4) {
            int k0 = (kc + 1) * 64 + aq * 16;
            if (k0 + 15 < NE) {
#pragma unroll
                for (int i = 0; i < 4; i++) *(float4*)&v[i * 4] = *(const float4*)(xrow + k0 + i * 4);
            } else {
#pragma unroll
                for (int i = 0; i < 16; i++) v[i] = (k0 + i < NE) ? xrow[k0 + i] : 0.0f;
            }
        }
#pragma unroll
        for (int s = 0; s < 4; s++) {
            uint32_t ah0[4], ah1[4];
            {
                int o = r0 * 128 + s * 32 + segb; o ^= ((o >> 3) & 0x70);
                ldsm4(ah0, sb + o);
            }
            {
                int o = r1 * 128 + s * 32 + segb; o ^= ((o >> 3) & 0x70);
                ldsm4(ah1, sb + o);
            }
            const __half* pb = g_Wp + (size_t)(kc * 4 + s) * 16384 + nbase;
#pragma unroll
            for (int f = 0; f < 8; f++) {
                uint2 bh = *(const uint2*)(pb + f * 128);
                MMA(acc[0][f], ah0, bh.x, bh.y);
                MMA(acc[1][f], ah1, bh.x, bh.y);
            }
        }
    }

    int rg = lane >> 2, c2 = (lane & 3) * 2;
#pragma unroll
    for (int f = 0; f < 8; f++) {
        int col = nt * 256 + warpN * 64 + f * 8 + c2;
        float2 bb = *(const float2*)&g_bias[col];
#pragma unroll
        for (int m = 0; m < 2; m++) {
            int row = mt * 128 + warpM * 32 + m * 16 + rg;
            *(uint32_t*)&g_x[(size_t)row * XN + col] =
                packh2(acc[m][f][0] + bb.x, acc[m][f][1] + bb.y);
            *(uint32_t*)&g_x[(size_t)(row + 8) * XN + col] =
                packh2(acc[m][f][2] + bb.x, acc[m][f][3] + bb.y);
        }
    }
}

// ---------------- winner/compact/prep: ALL steps in 3 launches ----------------
__global__ void k_winner_all(const int* __restrict__ td) {
    int t = blockIdx.y;
    int idx = blockIdx.x * blockDim.x + threadIdx.x;
    int b = idx >> 11, s = idx & 2047;
    int d = td[b * (NT * NS) + t * NS + s];
    atomicMax(&g_win[t * NROWS + (b << 11) + d], s);
}

__global__ void k_compact_all(const int* __restrict__ td) {
    __shared__ int scnt, sbase;
    int t = blockIdx.y;
    int tid = threadIdx.x;
    if (tid == 0) scnt = 0;
    __syncthreads();
    int idx = blockIdx.x * blockDim.x + tid;
    int b = idx >> 11, s = idx & 2047;
    int d = td[b * (NT * NS) + t * NS + s];
    int dd = (b << 11) + d;
    bool win = (d != 0) && (g_win[t * NROWS + dd] == s);
    int pos = 0;
    if (win) pos = atomicAdd(&scnt, 1);
    __syncthreads();
    if (tid == 0) sbase = atomicAdd(&g_cnt[t], scnt);
    __syncthreads();
    if (win) {
        g_work[t * NROWS + sbase + pos] = idx;
        atomicOr(&g_wmask[dd], 1u << t);
    }
}

// after wmask is complete: resolve all per-row offsets once
__global__ void k_prep_all(const int* __restrict__ td, const int* __restrict__ tl,
                           const int* __restrict__ tr) {
    int t = blockIdx.y;
    int i = blockIdx.x * blockDim.x + threadIdx.x;
    if (i >= g_cnt[t]) return;
    int idx = g_work[t * NROWS + i];
    int b = idx >> 11, s = idx & 2047;
    int tb = b * (NT * NS) + t * NS + s;
    int brow = b << 11;
    int rl = brow + tl[tb];
    int rr = brow + tr[tb];
    int rd = brow + td[tb];
    uint32_t below = (1u << t) - 1u;
    int nl = __popc(g_wmask[rl] & below);
    int nr = __popc(g_wmask[rr] & below);
    int nd = __popc(g_wmask[rd] & below);
    // readers use buf[(n+1)&1]; writer uses buf[n&1] -> never collide
    g_meta[t * NROWS + i] = make_int4(
        ((nl + 1) & 1) * HCNT + (rl << 8),
        ((nr + 1) & 1) * HCNT + (rr << 8),
        (nd & 1) * HCNT + (rd << 8),
        idx);
}

// ---------------- step 0: h==0 -> pure elementwise from x ----------------
__global__ void k_step0(__half* __restrict__ hhw, __half* __restrict__ hlw,
                        float* __restrict__ ccw) {
    int count = g_cnt[0];
    int tid = threadIdx.x;
    int m = blockIdx.x * 8 + (tid >> 5);
    if (m >= count) return;
    int lane = tid & 31;
    int4 v = g_meta[m];          // t = 0
    int eo = v.z + lane * 8;     // offD (buffer 0 at t=0)
    const uint4* xp = (const uint4*)(g_x + (size_t)v.w * XN + (size_t)lane * 32);
    uint4 xr[4];
#pragma unroll
    for (int i = 0; i < 4; i++) xr[i] = xp[i];
    const __half2* xh = (const __half2*)xr;
    float ho[8], co[8];
#pragma unroll
    for (int u = 0; u < 8; u++) {
        float2 p0 = __half22float2(xh[2 * u]);      // x_i, x_o
        float2 p1 = __half22float2(xh[2 * u + 1]);  // x_u, x_f
        float gi = sigm(p0.x);
        float go = sigm(p0.y);
        float gu = tanhf(p1.x);
        float cn = gi * gu;                          // c_l = c_r = 0
        ho[u] = go * tanhf(cn);
        co[u] = cn;
    }
    uint32_t hw[4], lw[4];
#pragma unroll
    for (int p = 0; p < 4; p++) {
        float v0 = ho[2 * p], v1 = ho[2 * p + 1];
        __half a = __float2half_rn(v0);
        __half bb = __float2half_rn(v1);
        hw[p] = packh2(v0, v1);
        lw[p] = packh2(v0 - __half2float(a), v1 - __half2float(bb));
    }
    *(uint4*)(hhw + eo) = make_uint4(hw[0], hw[1], hw[2], hw[3]);
    *(uint4*)(hlw + eo) = make_uint4(lw[0], lw[1], lw[2], lw[3]);
    *(float4*)(ccw + eo) = *(float4*)&co[0];
    *(float4*)(ccw + eo + 4) = *(float4*)&co[4];
}

// ---------------- fused step: fp16 mma, 3-buf pipeline, occupancy 2 ----------
// grid = (8, 512), 512 threads (16 warps: 4M x 4N), 2 CTAs/SM
__global__ __launch_bounds__(512, 2) void k_step_mma(
    int t,
    const __half* __restrict__ hh, const __half* __restrict__ hl,
    const float* __restrict__ cc,
    __half* __restrict__ hhw, __half* __restrict__ hlw, float* __restrict__ ccw)
{
    extern __shared__ char smem[];
    int tid = threadIdx.x;
    int count = g_cnt[t];
    int mt = blockIdx.y;
    if (mt * BM >= count) return;
    int nt = blockIdx.x;

    int* sL = (int*)(smem + OFF_IDX);
    int* sR = (int*)(smem + OFF_IDX + 512);
    int* sD = (int*)(smem + OFF_IDX + 1024);
    int* sRow = (int*)(smem + OFF_IDX + 1536);

    if (tid < BM) {
        int m = mt * BM + tid;
        int4 v = (m < count) ? g_meta[t * NROWS + m] : make_int4(0, 0, -1, 0);
        sL[tid] = v.x; sR[tid] = v.y; sD[tid] = v.z; sRow[tid] = v.w;
    }
    __syncthreads();

    uint32_t sb = smem_u32(smem);
    int arow = tid >> 2, aq = tid & 3;
    int offL = sL[arow], offR = sR[arow];
    int b0 = arow * 128 + aq * 32;
    int b1 = b0 + 16;
    int s0 = b0 ^ ((b0 >> 3) & 0x70);
    int s1 = b1 ^ ((b1 >> 3) & 0x70);
    const uint32_t offA[3] = {OFF_A0, OFF_A1, OFF_A2};

    // prologue: group 0 = chunk 0; group 1 = chunk 1
    {
        const __half* ph = hh + offL + aq * 16;
        cp16(sb + OFF_A0 + s0, ph);  cp16(sb + OFF_A0 + s1, ph + 8);
        CP_COMMIT;
        const __half* p1 = hh + offL + 64 + aq * 16;
        cp16(sb + OFF_A1 + s0, p1);  cp16(sb + OFF_A1 + s1, p1 + 8);
        CP_COMMIT;
    }

    int warp = tid >> 5, lane = tid & 31;
    int warpM = warp & 3, warpN = warp >> 2;

    float acc[2][5][4];
#pragma unroll
    for (int m = 0; m < 2; m++)
#pragma unroll
        for (int f = 0; f < 5; f++)
#pragma unroll
            for (int i = 0; i < 4; i++) acc[m][f][i] = 0.0f;

    int r0 = warpM * 32 + (lane & 15);
    int r1 = r0 + 16;
    int segb = ((lane >> 4) & 1) * 16;

    int tilesel = nt * 2 + (warpN >> 1);
    const __half* pbh = g_UBH + (size_t)tilesel * UB_NT_STRIDE;
    int lanepart = (lane >> 2) * 16 + (lane & 3) * 4;
    int warppart = (warpN & 1) * 640;

    for (int kc = 0; kc < 8; kc++) {
        if (kc < 7) { CP_WAIT1; } else { CP_WAIT0; }
        __syncthreads();          // chunk kc visible to ALL warps; buf[(kc+2)%3] free
        if (kc < 6) {
            int kcn = kc + 2;
            int off = (kcn < 4) ? offL : offR;
            int k0 = (kcn & 3) * 64;
            const __half* ph = hh + off + k0 + aq * 16;
            uint32_t ab = sb + offA[kcn % 3];
            cp16(ab + s0, ph);  cp16(ab + s1, ph + 8);
            CP_COMMIT;
        }
        uint32_t abh = sb + offA[kc % 3];
#pragma unroll
        for (int s = 0; s < 4; s++) {
            uint32_t ah0[4], ah1[4];
            {
                int o = r0 * 128 + s * 32 + segb; o ^= ((o >> 3) & 0x70);
                ldsm4(ah0, abh + o);
            }
            {
                int o = r1 * 128 + s * 32 + segb; o ^= ((o >> 3) & 0x70);
                ldsm4(ah1, abh + o);
            }
            int be = (kc * 4 + s) * 1280 + warppart + lanepart;
#pragma unroll
            for (int f = 0; f < 5; f++) {
                uint2 bh = *(const uint2*)(pbh + be + f * 128);
                MMA(acc[0][f], ah0, bh.x, bh.y);
                MMA(acc[1][f], ah1, bh.x, bh.y);
            }
        }
    }
    __syncthreads();    // all MMA reads done before stage-region overwrite

    // epilogue: transpose acc through smem, fuse activations (direct LDG x/c)
    float* stg = (float*)(smem + OFF_STAGE);
    {
        int rg = lane >> 2, cl = 2 * (lane & 3);
#pragma unroll
        for (int m = 0; m < 2; m++) {
#pragma unroll
            for (int f = 0; f < 5; f++) {
                int row = warpM * 32 + m * 16 + rg;
                int col = warpN * 40 + f * 8 + cl;
                *(float2*)&stg[row * 164 + col] = make_float2(acc[m][f][0], acc[m][f][1]);
                *(float2*)&stg[(row + 8) * 164 + col] = make_float2(acc[m][f][2], acc[m][f][3]);
            }
        }
    }
    __syncthreads();

    {
        int row = arow, ug = aq;
        int j0 = nt * 32;
        int od = sD[row];
        const uint4* xp = (const uint4*)(g_x + (size_t)sRow[row] * XN + (size_t)(j0 + ug * 8) * 4);
        const float* clp = cc + offL + j0 + ug * 8;
        const float* crp = cc + offR + j0 + ug * 8;
        uint4 xr[4];
#pragma unroll
        for (int i = 0; i < 4; i++) xr[i] = xp[i];
        const __half2* xh = (const __half2*)xr;
        float clv[8], crv[8], ho[8], co[8];
        *(float4*)&clv[0] = *(const float4*)clp;
        *(float4*)&clv[4] = *(const float4*)(clp + 4);
        *(float4*)&crv[0] = *(const float4*)crp;
        *(float4*)&crv[4] = *(const float4*)(crp + 4);
#pragma unroll
        for (int u = 0; u < 8; u++) {
            int col = (ug * 8 + u) * 5;
            float a_i  = stg[row * 164 + col + 0];
            float a_o  = stg[row * 164 + col + 1];
            float a_u  = stg[row * 164 + col + 2];
            float a_fl = stg[row * 164 + col + 3];
            float a_fr = stg[row * 164 + col + 4];
            float2 p0 = __half22float2(xh[2 * u]);
            float2 p1 = __half22float2(xh[2 * u + 1]);
            float gi = sigm(a_i + p0.x);
            float go = sigm(a_o + p0.y);
            float gu = tanhf(a_u + p1.x);
            float fl = sigm(a_fl + p1.y);
            float fr = sigm(a_fr + p1.y);
            float cnew = gi * gu + fl * clv[u] + fr * crv[u];
            ho[u] = go * tanhf(cnew);
            co[u] = cnew;
        }
        if (od >= 0) {
            uint32_t hw[4], lw[4];
#pragma unroll
            for (int p = 0; p < 4; p++) {
                float v0 = ho[2 * p], v1 = ho[2 * p + 1];
                __half a = __float2half_rn(v0);
                __half b = __float2half_rn(v1);
                hw[p] = packh2(v0, v1);
                lw[p] = packh2(v0 - __half2float(a), v1 - __half2float(b));
            }
            int eo = od + j0 + ug * 8;
            *(uint4*)(hhw + eo) = make_uint4(hw[0], hw[1], hw[2], hw[3]);
            *(uint4*)(hlw + eo) = make_uint4(lw[0], lw[1], lw[2], lw[3]);
            *(float4*)(ccw + eo) = *(float4*)&co[0];
            *(float4*)(ccw + eo + 4) = *(float4*)&co[4];
        }
    }
}

// ---------------- final output assembly ----------------
__global__ void k_output(const __half* __restrict__ hh, const __half* __restrict__ hl,
                         const float* __restrict__ cc,
                         float* __restrict__ oh, float* __restrict__ oc) {
    int tid = threadIdx.x;
    int row = blockIdx.x * 16 + (tid >> 5);
    int cg = (tid & 31) * 8;
    size_t oo = ((size_t)row << 8) + cg;
    uint32_t m = g_wmask[row];
    if (m == 0u) {
        float4 z = make_float4(0.f, 0.f, 0.f, 0.f);
        *(float4*)(oh + oo) = z; *(float4*)(oh + oo + 4) = z;
        *(float4*)(oc + oo) = z; *(float4*)(oc + oo + 4) = z;
        return;
    }
    int nw = __popc(m);
    size_t so = (size_t)(((nw - 1) & 1)) * HCNT + oo;
    uint4 rh = *(const uint4*)(hh + so);
    uint4 rl = *(const uint4*)(hl + so);
    const __half2* ph = (const __half2*)&rh;
    const __half2* pl = (const __half2*)&rl;
#pragma unroll
    for (int i = 0; i < 4; i++) {
        float2 a = __half22float2(ph[i]);
        float2 b = __half22float2(pl[i]);
        *(float2*)(oh + oo + 2 * i) = make_float2(a.x + b.x, a.y + b.y);
    }
    *(float4*)(oc + oo) = *(const float4*)(cc + so);
    *(float4*)(oc + oo + 4) = *(const float4*)(cc + so + 4);
}

// ---------------- h_root ----------------
__global__ void k_root(const int* __restrict__ td, const float* __restrict__ out_h,
                       float* __restrict__ out_root) {
    __shared__ int red[256];
    int b = blockIdx.x, tid = threadIdx.x;
    int v = 0;
    for (int s = tid; s < NS; s += 256) v = max(v, td[b * (NT * NS) + (NT - 1) * NS + s]);
    red[tid] = v;
    __syncthreads();
    for (int off = 128; off > 0; off >>= 1) {
        if (tid < off) red[tid] = max(red[tid], red[tid + off]);
        __syncthreads();
    }
    int root = red[0];
    out_root[b * NH + tid] = out_h[(((size_t)(b << 11)) + root) * NH + tid];
}

// ---------------- host launcher (graph-capturable) ----------------
extern "C" void kernel_launch(void* const* d_in, const int* in_sizes, int n_in,
                              void* d_out, int out_size) {
    const float* X     = (const float*)d_in[0];
    const int*   td    = (const int*)d_in[1];
    const int*   tr    = (const int*)d_in[2];
    const int*   tl    = (const int*)d_in[3];
    const float* W_iou = (const float*)d_in[4];
    const float* b_iou = (const float*)d_in[5];
    const float* U_l   = (const float*)d_in[6];
    const float* U_r   = (const float*)d_in[7];
    const float* W_f   = (const float*)d_in[8];
    const float* b_f   = (const float*)d_in[9];
    const float* F_ll  = (const float*)d_in[10];
    const float* F_lr  = (const float*)d_in[11];
    const float* F_rl  = (const float*)d_in[12];
    const float* F_rr  = (const float*)d_in[13];

    float* out      = (float*)d_out;
    float* out_h    = out;
    float* out_c    = out + (size_t)HCNT;
    float* out_root = out + 2 * (size_t)HCNT;

    __half *hhb = nullptr, *hlb = nullptr;
    float* cb = nullptr;
    cudaGetSymbolAddress((void**)&hhb, g_hh);
    cudaGetSymbolAddress((void**)&hlb, g_hl);
    cudaGetSymbolAddress((void**)&cb, g_c);

    static int attr_done = 0;
    if (!attr_done) {
        cudaFuncSetAttribute(k_step_mma, cudaFuncAttributeMaxDynamicSharedMemorySize, SMEM_DYN);
        attr_done = 1;
    }

    k_init<<<4096, 256>>>();
    k_pack_wp<<<(WP_TOTAL + 255) / 256, 256>>>(W_iou, b_iou, W_f, b_f);
    k_pack_ub<<<(UB_TOTAL + 255) / 256, 256>>>(U_l, U_r, F_ll, F_lr, F_rl, F_rr);
    k_winner_all<<<dim3(NROWS / 256, NT), 256>>>(td);
    k_compact_all<<<dim3(NROWS / 256, NT), 256>>>(td);
    k_prep_all<<<dim3(NROWS / 256, NT), 256>>>(td, tl, tr);
    k_xgemm_mma<<<dim3(512, 4), 512>>>(X);

    k_step0<<<NROWS / 8, 256>>>(hhb, hlb, cb);
    for (int t = 1; t < NT; t++) {
        k_step_mma<<<dim3(NTL, 512), 512, SMEM_DYN>>>(
            t, hhb, hlb, cb, hhb, hlb, cb);
    }
    k_output<<<4096, 512>>>(hhb, hlb, cb, out_h, out_c);
    k_root<<<NB, 256>>>(td, out_h, out_root);
}

// round 17
// speedup vs baseline: 1.4263x; 1.4263x over previous
#include <cuda_runtime.h>
#include <cuda_fp16.h>
#include <math.h>
#include <stdint.h>

// ---------------- problem constants ----------------
#define NB 32
#define NS 2048
#define NE 300
#define NH 256
#define NT 24
#define NROWS 65536            // NB*NS
#define XN 1024                 // x-gates per row: j*4 + {i,o,u,f}
#define HCNT 16777216           // NROWS*NH

// ---------------- step-GEMM tiling ----------------
#define BM 128                  // rows per CTA
#define NTL 8                   // 1280 / 160 n-tiles
#define UB_NT_STRIDE 40960      // fp16 elems per 80-col packed tile (8 kchunks)
#define UB_TOTAL (16 * UB_NT_STRIDE)
#define WP_TOTAL (20 * 16384)   // W pack: 20 kcs * 1024 cols * 16

// ---------------- k_step dynamic smem (bytes) ------
// occupancy-2 layout: 86016 B/CTA -> 2 CTAs/SM (172 KB of 228 KB)
#define OFF_IDX   0             // sL/sR/sD/sRow: 4 * 512
#define OFF_A0    2048          // 3 x (128 x 64 fp16 = 16384)
#define OFF_A1    18432
#define OFF_A2    34816
#define OFF_STAGE 2048          // 128 x 164 f32 = 83968 (reuses A bufs)
#define SMEM_DYN  86016

// ---------------- device scratch -------------------
__device__ __half g_x[(size_t)NROWS * XN];    // 128 MiB packed x-gates (fp16)
__device__ __half g_Wp[WP_TOTAL];             // W fragment-native fp16 hi
__device__ float g_bias[XN];
__device__ __half g_UBH[UB_TOTAL];            // U fragment-native fp16 hi
__device__ __half g_hh[2 * (size_t)HCNT];     // h hi, 2 alternation buffers
__device__ __half g_hl[2 * (size_t)HCNT];     // h lo
__device__ float g_c[2 * (size_t)HCNT];       // c fp32
__device__ int      g_win[NT * NROWS];        // per-step winner s for each (b,d)
__device__ uint32_t g_wmask[NROWS];           // bit t: row won at step t
__device__ int      g_work[NT * NROWS];       // per-step compacted winner lists
__device__ int4     g_meta[NT * NROWS];       // per-step {offL, offR, offD, row}
__device__ int      g_cnt[NT];

__device__ __forceinline__ float sigm(float x) { return 1.0f / (1.0f + __expf(-x)); }

__device__ __forceinline__ uint32_t smem_u32(const void* p) {
    uint32_t r;
    asm("{ .reg .u64 t; cvta.to.shared.u64 t, %1; cvt.u32.u64 %0, t; }" : "=r"(r) : "l"(p));
    return r;
}
__device__ __forceinline__ void ldsm4(uint32_t* r, uint32_t addr) {
    asm volatile("ldmatrix.sync.aligned.m8n8.x4.shared.b16 {%0,%1,%2,%3}, [%4];"
                 : "=r"(r[0]), "=r"(r[1]), "=r"(r[2]), "=r"(r[3]) : "r"(addr));
}
#define MMA(d, a, bx, by) asm volatile( \
    "mma.sync.aligned.m16n8k16.row.col.f32.f16.f16.f32 " \
    "{%0,%1,%2,%3},{%4,%5,%6,%7},{%8,%9},{%0,%1,%2,%3};" \
    : "+f"((d)[0]), "+f"((d)[1]), "+f"((d)[2]), "+f"((d)[3]) \
    : "r"((a)[0]), "r"((a)[1]), "r"((a)[2]), "r"((a)[3]), "r"(bx), "r"(by))

__device__ __forceinline__ void cp16(uint32_t dst, const void* src) {
    asm volatile("{\n\t.reg .u64 g;\n\tcvta.to.global.u64 g, %1;\n\t"
                 "cp.async.cg.shared.global [%0], [g], 16;\n\t}"
                 :: "r"(dst), "l"(src) : "memory");
}
#define CP_COMMIT asm volatile("cp.async.commit_group;" ::: "memory")
#define CP_WAIT1  asm volatile("cp.async.wait_group 1;" ::: "memory")
#define CP_WAIT0  asm volatile("cp.async.wait_group 0;" ::: "memory")

__device__ __forceinline__ uint32_t packh2(float a, float b) {
    __half2 v = __floats2half2_rn(a, b);
    return *(uint32_t*)&v;
}

// ---------------- init: zero ONLY buffer 1 of state (buf0 always written
// before first read: readers with n prior writes read buf[(n+1)&1]) ----------
__global__ void k_init() {
    size_t i = (size_t)blockIdx.x * blockDim.x + threadIdx.x;
    size_t stride = (size_t)gridDim.x * blockDim.x;
    uint32_t* ph = (uint32_t*)g_hh;   // u32 p covers halves 2p,2p+1
    uint32_t* pl = (uint32_t*)g_hl;
    for (size_t p = (size_t)(HCNT / 2) + i; p < (size_t)HCNT; p += stride) {
        ph[p] = 0u; pl[p] = 0u;
    }
    for (size_t p = (size_t)HCNT + i; p < 2 * (size_t)HCNT; p += stride) g_c[p] = 0.0f;
    for (size_t p = i; p < (size_t)(NT * NROWS); p += stride) g_win[p] = -1;
    for (size_t p = i; p < (size_t)NROWS; p += stride) g_wmask[p] = 0u;
    if (i < NT) g_cnt[i] = 0;
}

// ---- pack W: fragment-native fp16 hi; also bias ----
__global__ void k_pack_wp(const float* __restrict__ W_iou, const float* __restrict__ b_iou,
                          const float* __restrict__ W_f,   const float* __restrict__ b_f) {
    int idx = blockIdx.x * blockDim.x + threadIdx.x;
    if (idx < WP_TOTAL) {
        int kcs = idx >> 14;
        int rem = idx & 16383;
        int ncol = rem >> 4, low = rem & 15;
        int c = low >> 2, e = low & 3;
        int kin = (e < 2) ? (2 * c + e) : (8 + 2 * c + (e - 2));
        int k = (kcs >> 2) * 64 + (kcs & 3) * 16 + kin;
        int j = ncol >> 2, g = ncol & 3;
        float v = 0.0f;
        if (k < NE) v = (g < 3) ? W_iou[k * 768 + g * 256 + j] : W_f[k * 256 + j];
        g_Wp[idx] = __float2half_rn(v);
    }
    if (idx < XN) {
        int j = idx >> 2, g = idx & 3;
        g_bias[idx] = (g < 3) ? b_iou[g * 256 + j] : b_f[j];
    }
}

// ---- pack U: fragment-native fp16 hi (16 tiles of 80 cols) ----
__global__ void k_pack_ub(const float* __restrict__ Ul, const float* __restrict__ Ur,
                          const float* __restrict__ Fll, const float* __restrict__ Flr,
                          const float* __restrict__ Frl, const float* __restrict__ Frr) {
    int idx = blockIdx.x * blockDim.x + threadIdx.x;
    if (idx >= UB_TOTAL) return;
    int e = idx & 3, c = (idx >> 2) & 3;
    int n = (idx >> 4) % 80;
    int q = (idx >> 4) / 80;           // ntl*32 + kc*4 + s
    int s = q & 3, kc = (q >> 2) & 7, ntl = q >> 5;
    int kin = (e < 2) ? (2 * c + e) : (8 + 2 * c + (e - 2));
    int k = kc * 64 + s * 16 + kin;
    int ncol = ntl * 80 + n;
    int j = ncol / 5, g = ncol - 5 * j;
    float v;
    if (k < 256) {
        v = (g == 0) ? Ul[k * 768 + j]
          : (g == 1) ? Ul[k * 768 + 256 + j]
          : (g == 2) ? Ul[k * 768 + 512 + j]
          : (g == 3) ? Fll[k * 256 + j]
                     : Frl[k * 256 + j];
    } else {
        int kr = k - 256;
        v = (g == 0) ? Ur[kr * 768 + j]
          : (g == 1) ? Ur[kr * 768 + 256 + j]
          : (g == 2) ? Ur[kr * 768 + 512 + j]
          : (g == 3) ? Flr[kr * 256 + j]
                     : Frr[kr * 256 + j];
    }
    g_UBH[idx] = __float2half_rn(v);
}

// ---------------- tensorized x-projection: g_x = fp16(X @ W + b) ----------------
// single-pass A-hi (x already stored fp16; A-lo pass below x-storage noise)
__global__ __launch_bounds__(512, 1) void k_xgemm_mma(const float* __restrict__ X) {
    __shared__ __align__(16) char xs[16384];   // AH only
    int mt = blockIdx.x, nt = blockIdx.y;
    int tid = threadIdx.x;
    int warp = tid >> 5, lane = tid & 31;
    int warpM = warp & 3, warpN = warp >> 2;
    uint32_t sb = smem_u32(xs);

    int arow = tid >> 2, aq = tid & 3;
    int b0 = arow * 128 + aq * 32;
    int s0 = b0 ^ ((b0 >> 3) & 0x70);
    int s1 = (b0 + 16) ^ (((b0 + 16) >> 3) & 0x70);
    const float* xrow = X + (size_t)(mt * 128 + arow) * NE;

    float acc[2][8][4];
#pragma unroll
    for (int m = 0; m < 2; m++)
#pragma unroll
        for (int f = 0; f < 8; f++)
#pragma unroll
            for (int i = 0; i < 4; i++) acc[m][f][i] = 0.0f;

    int r0 = warpM * 32 + (lane & 15);
    int r1 = r0 + 16;
    int segb = ((lane >> 4) & 1) * 16;
    int lanepart = (lane >> 2) * 16 + (lane & 3) * 4;
    int nbase = (nt * 256 + warpN * 64) * 16 + lanepart;

    float v[16];
    {
        int k0 = aq * 16;
#pragma unroll
        for (int i = 0; i < 4; i++) *(float4*)&v[i * 4] = *(const float4*)(xrow + k0 + i * 4);
    }

    for (int kc = 0; kc < 5; kc++) {
        __syncthreads();
        {
            uint4 ph;
            uint32_t* hp = (uint32_t*)&ph;
#pragma unroll
            for (int p = 0; p < 4; p++) hp[p] = packh2(v[2 * p], v[2 * p + 1]);
            *(uint4*)(xs + s0) = ph;
#pragma unroll
            for (int p = 0; p < 4; p++) hp[p] = packh2(v[8 + 2 * p], v[8 + 2 * p + 1]);
            *(uint4*)(xs + s1) = ph;
        }
        __syncthreads();
        if (kc < 4) {
            int k0 = (kc + 1) * 64 + aq * 16;
            if (k0 + 15 < NE) {
#pragma unroll
                for (int i = 0; i < 4; i++) *(float4*)&v[i * 4] = *(const float4*)(xrow + k0 + i * 4);
            } else {
#pragma unroll
                for (int i = 0; i < 16; i++) v[i] = (k0 + i < NE) ? xrow[k0 + i] : 0.0f;
            }
        }
#pragma unroll
        for (int s = 0; s < 4; s++) {
            uint32_t ah0[4], ah1[4];
            {
                int o = r0 * 128 + s * 32 + segb; o ^= ((o >> 3) & 0x70);
                ldsm4(ah0, sb + o);
            }
            {
                int o = r1 * 128 + s * 32 + segb; o ^= ((o >> 3) & 0x70);
                ldsm4(ah1, sb + o);
            }
            const __half* pb = g_Wp + (size_t)(kc * 4 + s) * 16384 + nbase;
#pragma unroll
            for (int f = 0; f < 8; f++) {
                uint2 bh = *(const uint2*)(pb + f * 128);
                MMA(acc[0][f], ah0, bh.x, bh.y);
                MMA(acc[1][f], ah1, bh.x, bh.y);
            }
        }
    }

    int rg = lane >> 2, c2 = (lane & 3) * 2;
#pragma unroll
    for (int f = 0; f < 8; f++) {
        int col = nt * 256 + warpN * 64 + f * 8 + c2;
        float2 bb = *(const float2*)&g_bias[col];
#pragma unroll
        for (int m = 0; m < 2; m++) {
            int row = mt * 128 + warpM * 32 + m * 16 + rg;
            *(uint32_t*)&g_x[(size_t)row * XN + col] =
                packh2(acc[m][f][0] + bb.x, acc[m][f][1] + bb.y);
            *(uint32_t*)&g_x[(size_t)(row + 8) * XN + col] =
                packh2(acc[m][f][2] + bb.x, acc[m][f][3] + bb.y);
        }
    }
}

// ---------------- winner/compact/prep: ALL steps in 3 launches ----------------
__global__ void k_winner_all(const int* __restrict__ td) {
    int t = blockIdx.y;
    int idx = blockIdx.x * blockDim.x + threadIdx.x;
    int b = idx >> 11, s = idx & 2047;
    int d = td[b * (NT * NS) + t * NS + s];
    atomicMax(&g_win[t * NROWS + (b << 11) + d], s);
}

__global__ void k_compact_all(const int* __restrict__ td) {
    __shared__ int scnt, sbase;
    int t = blockIdx.y;
    int tid = threadIdx.x;
    if (tid == 0) scnt = 0;
    __syncthreads();
    int idx = blockIdx.x * blockDim.x + tid;
    int b = idx >> 11, s = idx & 2047;
    int d = td[b * (NT * NS) + t * NS + s];
    int dd = (b << 11) + d;
    bool win = (d != 0) && (g_win[t * NROWS + dd] == s);
    int pos = 0;
    if (win) pos = atomicAdd(&scnt, 1);
    __syncthreads();
    if (tid == 0) sbase = atomicAdd(&g_cnt[t], scnt);
    __syncthreads();
    if (win) {
        g_work[t * NROWS + sbase + pos] = idx;
        atomicOr(&g_wmask[dd], 1u << t);
    }
}

// after wmask is complete: resolve all per-row offsets once
__global__ void k_prep_all(const int* __restrict__ td, const int* __restrict__ tl,
                           const int* __restrict__ tr) {
    int t = blockIdx.y;
    int i = blockIdx.x * blockDim.x + threadIdx.x;
    if (i >= g_cnt[t]) return;
    int idx = g_work[t * NROWS + i];
    int b = idx >> 11, s = idx & 2047;
    int tb = b * (NT * NS) + t * NS + s;
    int brow = b << 11;
    int rl = brow + tl[tb];
    int rr = brow + tr[tb];
    int rd = brow + td[tb];
    uint32_t below = (1u << t) - 1u;
    int nl = __popc(g_wmask[rl] & below);
    int nr = __popc(g_wmask[rr] & below);
    int nd = __popc(g_wmask[rd] & below);
    // readers use buf[(n+1)&1]; writer uses buf[n&1] -> never collide
    g_meta[t * NROWS + i] = make_int4(
        ((nl + 1) & 1) * HCNT + (rl << 8),
        ((nr + 1) & 1) * HCNT + (rr << 8),
        (nd & 1) * HCNT + (rd << 8),
        idx);
}

// ---------------- step 0: h==0 -> pure elementwise from x ----------------
__global__ void k_step0(__half* __restrict__ hhw, __half* __restrict__ hlw,
                        float* __restrict__ ccw) {
    int count = g_cnt[0];
    int tid = threadIdx.x;
    int m = blockIdx.x * 8 + (tid >> 5);
    if (m >= count) return;
    int lane = tid & 31;
    int4 v = g_meta[m];          // t = 0
    int eo = v.z + lane * 8;     // offD (buffer 0 at t=0)
    const uint4* xp = (const uint4*)(g_x + (size_t)v.w * XN + (size_t)lane * 32);
    uint4 xr[4];
#pragma unroll
    for (int i = 0; i < 4; i++) xr[i] = xp[i];
    const __half2* xh = (const __half2*)xr;
    float ho[8], co[8];
#pragma unroll
    for (int u = 0; u < 8; u++) {
        float2 p0 = __half22float2(xh[2 * u]);      // x_i, x_o
        float2 p1 = __half22float2(xh[2 * u + 1]);  // x_u, x_f
        float gi = sigm(p0.x);
        float go = sigm(p0.y);
        float gu = tanhf(p1.x);
        float cn = gi * gu;                          // c_l = c_r = 0
        ho[u] = go * tanhf(cn);
        co[u] = cn;
    }
    uint32_t hw[4], lw[4];
#pragma unroll
    for (int p = 0; p < 4; p++) {
        float v0 = ho[2 * p], v1 = ho[2 * p + 1];
        __half a = __float2half_rn(v0);
        __half bb = __float2half_rn(v1);
        hw[p] = packh2(v0, v1);
        lw[p] = packh2(v0 - __half2float(a), v1 - __half2float(bb));
    }
    *(uint4*)(hhw + eo) = make_uint4(hw[0], hw[1], hw[2], hw[3]);
    *(uint4*)(hlw + eo) = make_uint4(lw[0], lw[1], lw[2], lw[3]);
    *(float4*)(ccw + eo) = *(float4*)&co[0];
    *(float4*)(ccw + eo + 4) = *(float4*)&co[4];
}

// ---------------- fused step: fp16 mma, 3-buf pipeline, occupancy 2 ----------
// grid = (8, 512), 512 threads (16 warps: 4M x 4N), 2 CTAs/SM
__global__ __launch_bounds__(512, 2) void k_step_mma(
    int t,
    const __half* __restrict__ hh, const __half* __restrict__ hl,
    const float* __restrict__ cc,
    __half* __restrict__ hhw, __half* __restrict__ hlw, float* __restrict__ ccw)
{
    extern __shared__ char smem[];
    int tid = threadIdx.x;
    int count = g_cnt[t];
    int mt = blockIdx.y;
    if (mt * BM >= count) return;
    int nt = blockIdx.x;

    int* sL = (int*)(smem + OFF_IDX);
    int* sR = (int*)(smem + OFF_IDX + 512);
    int* sD = (int*)(smem + OFF_IDX + 1024);
    int* sRow = (int*)(smem + OFF_IDX + 1536);

    if (tid < BM) {
        int m = mt * BM + tid;
        int4 v = (m < count) ? g_meta[t * NROWS + m] : make_int4(0, 0, -1, 0);
        sL[tid] = v.x; sR[tid] = v.y; sD[tid] = v.z; sRow[tid] = v.w;
    }
    __syncthreads();

    uint32_t sb = smem_u32(smem);
    int arow = tid >> 2, aq = tid & 3;
    int offL = sL[arow], offR = sR[arow];
    int b0 = arow * 128 + aq * 32;
    int b1 = b0 + 16;
    int s0 = b0 ^ ((b0 >> 3) & 0x70);
    int s1 = b1 ^ ((b1 >> 3) & 0x70);
    const uint32_t offA[3] = {OFF_A0, OFF_A1, OFF_A2};

    // prologue: group 0 = chunk 0; group 1 = chunk 1
    {
        const __half* ph = hh + offL + aq * 16;
        cp16(sb + OFF_A0 + s0, ph);  cp16(sb + OFF_A0 + s1, ph + 8);
        CP_COMMIT;
        const __half* p1 = hh + offL + 64 + aq * 16;
        cp16(sb + OFF_A1 + s0, p1);  cp16(sb + OFF_A1 + s1, p1 + 8);
        CP_COMMIT;
    }

    int warp = tid >> 5, lane = tid & 31;
    int warpM = warp & 3, warpN = warp >> 2;

    float acc[2][5][4];
#pragma unroll
    for (int m = 0; m < 2; m++)
#pragma unroll
        for (int f = 0; f < 5; f++)
#pragma unroll
            for (int i = 0; i < 4; i++) acc[m][f][i] = 0.0f;

    int r0 = warpM * 32 + (lane & 15);
    int r1 = r0 + 16;
    int segb = ((lane >> 4) & 1) * 16;

    int tilesel = nt * 2 + (warpN >> 1);
    const __half* pbh = g_UBH + (size_t)tilesel * UB_NT_STRIDE;
    int lanepart = (lane >> 2) * 16 + (lane & 3) * 4;
    int warppart = (warpN & 1) * 640;

    for (int kc = 0; kc < 8; kc++) {
        if (kc < 7) { CP_WAIT1; } else { CP_WAIT0; }
        __syncthreads();          // chunk kc visible to ALL warps; buf[(kc+2)%3] free
        if (kc < 6) {
            int kcn = kc + 2;
            int off = (kcn < 4) ? offL : offR;
            int k0 = (kcn & 3) * 64;
            const __half* ph = hh + off + k0 + aq * 16;
            uint32_t ab = sb + offA[kcn % 3];
            cp16(ab + s0, ph);  cp16(ab + s1, ph + 8);
            CP_COMMIT;
        }
        uint32_t abh = sb + offA[kc % 3];
#pragma unroll
        for (int s = 0; s < 4; s++) {
            uint32_t ah0[4], ah1[4];
            {
                int o = r0 * 128 + s * 32 + segb; o ^= ((o >> 3) & 0x70);
                ldsm4(ah0, abh + o);
            }
            {
                int o = r1 * 128 + s * 32 + segb; o ^= ((o >> 3) & 0x70);
                ldsm4(ah1, abh + o);
            }
            int be = (kc * 4 + s) * 1280 + warppart + lanepart;
#pragma unroll
            for (int f = 0; f < 5; f++) {
                uint2 bh = *(const uint2*)(pbh + be + f * 128);
                MMA(acc[0][f], ah0, bh.x, bh.y);
                MMA(acc[1][f], ah1, bh.x, bh.y);
            }
        }
    }
    __syncthreads();    // all MMA reads done before stage-region overwrite

    // epilogue: transpose acc through smem, fuse activations (direct LDG x/c)
    float* stg = (float*)(smem + OFF_STAGE);
    {
        int rg = lane >> 2, cl = 2 * (lane & 3);
#pragma unroll
        for (int m = 0; m < 2; m++) {
#pragma unroll
            for (int f = 0; f < 5; f++) {
                int row = warpM * 32 + m * 16 + rg;
                int col = warpN * 40 + f * 8 + cl;
                *(float2*)&stg[row * 164 + col] = make_float2(acc[m][f][0], acc[m][f][1]);
                *(float2*)&stg[(row + 8) * 164 + col] = make_float2(acc[m][f][2], acc[m][f][3]);
            }
        }
    }
    __syncthreads();

    {
        int row = arow, ug = aq;
        int j0 = nt * 32;
        int od = sD[row];
        const uint4* xp = (const uint4*)(g_x + (size_t)sRow[row] * XN + (size_t)(j0 + ug * 8) * 4);
        const float* clp = cc + offL + j0 + ug * 8;
        const float* crp = cc + offR + j0 + ug * 8;
        uint4 xr[4];
#pragma unroll
        for (int i = 0; i < 4; i++) xr[i] = xp[i];
        const __half2* xh = (const __half2*)xr;
        float clv[8], crv[8], ho[8], co[8];
        *(float4*)&clv[0] = *(const float4*)clp;
        *(float4*)&clv[4] = *(const float4*)(clp + 4);
        *(float4*)&crv[0] = *(const float4*)crp;
        *(float4*)&crv[4] = *(const float4*)(crp + 4);
#pragma unroll
        for (int u = 0; u < 8; u++) {
            int col = (ug * 8 + u) * 5;
            float a_i  = stg[row * 164 + col + 0];
            float a_o  = stg[row * 164 + col + 1];
            float a_u  = stg[row * 164 + col + 2];
            float a_fl = stg[row * 164 + col + 3];
            float a_fr = stg[row * 164 + col + 4];
            float2 p0 = __half22float2(xh[2 * u]);
            float2 p1 = __half22float2(xh[2 * u + 1]);
            float gi = sigm(a_i + p0.x);
            float go = sigm(a_o + p0.y);
            float gu = tanhf(a_u + p1.x);
            float fl = sigm(a_fl + p1.y);
            float fr = sigm(a_fr + p1.y);
            float cnew = gi * gu + fl * clv[u] + fr * crv[u];
            ho[u] = go * tanhf(cnew);
            co[u] = cnew;
        }
        if (od >= 0) {
            uint32_t hw[4], lw[4];
#pragma unroll
            for (int p = 0; p < 4; p++) {
                float v0 = ho[2 * p], v1 = ho[2 * p + 1];
                __half a = __float2half_rn(v0);
                __half b = __float2half_rn(v1);
                hw[p] = packh2(v0, v1);
                lw[p] = packh2(v0 - __half2float(a), v1 - __half2float(b));
            }
            int eo = od + j0 + ug * 8;
            *(uint4*)(hhw + eo) = make_uint4(hw[0], hw[1], hw[2], hw[3]);
            *(uint4*)(hlw + eo) = make_uint4(lw[0], lw[1], lw[2], lw[3]);
            *(float4*)(ccw + eo) = *(float4*)&co[0];
            *(float4*)(ccw + eo + 4) = *(float4*)&co[4];
        }
    }
}

// ---------------- final output assembly ----------------
__global__ void k_output(const __half* __restrict__ hh, const __half* __restrict__ hl,
                         const float* __restrict__ cc,
                         float* __restrict__ oh, float* __restrict__ oc) {
    int tid = threadIdx.x;
    int row = blockIdx.x * 16 + (tid >> 5);
    int cg = (tid & 31) * 8;
    size_t oo = ((size_t)row << 8) + cg;
    uint32_t m = g_wmask[row];
    if (m == 0u) {
        float4 z = make_float4(0.f, 0.f, 0.f, 0.f);
        *(float4*)(oh + oo) = z; *(float4*)(oh + oo + 4) = z;
        *(float4*)(oc + oo) = z; *(float4*)(oc + oo + 4) = z;
        return;
    }
    int nw = __popc(m);
    size_t so = (size_t)(((nw - 1) & 1)) * HCNT + oo;
    uint4 rh = *(const uint4*)(hh + so);
    uint4 rl = *(const uint4*)(hl + so);
    const __half2* ph = (const __half2*)&rh;
    const __half2* pl = (const __half2*)&rl;
#pragma unroll
    for (int i = 0; i < 4; i++) {
        float2 a = __half22float2(ph[i]);
        float2 b = __half22float2(pl[i]);
        *(float2*)(oh + oo + 2 * i) = make_float2(a.x + b.x, a.y + b.y);
    }
    *(float4*)(oc + oo) = *(const float4*)(cc + so);
    *(float4*)(oc + oo + 4) = *(const float4*)(cc + so + 4);
}

// ---------------- h_root ----------------
__global__ void k_root(const int* __restrict__ td, const float* __restrict__ out_h,
                       float* __restrict__ out_root) {
    __shared__ int red[256];
    int b = blockIdx.x, tid = threadIdx.x;
    int v = 0;
    for (int s = tid; s < NS; s += 256) v = max(v, td[b * (NT * NS) + (NT - 1) * NS + s]);
    red[tid] = v;
    __syncthreads();
    for (int off = 128; off > 0; off >>= 1) {
        if (tid < off) red[tid] = max(red[tid], red[tid + off]);
        __syncthreads();
    }
    int root = red[0];
    out_root[b * NH + tid] = out_h[(((size_t)(b << 11)) + root) * NH + tid];
}

// ---------------- host launcher (graph-capturable) ----------------
extern "C" void kernel_launch(void* const* d_in, const int* in_sizes, int n_in,
                              void* d_out, int out_size) {
    const float* X     = (const float*)d_in[0];
    const int*   td    = (const int*)d_in[1];
    const int*   tr    = (const int*)d_in[2];
    const int*   tl    = (const int*)d_in[3];
    const float* W_iou = (const float*)d_in[4];
    const float* b_iou = (const float*)d_in[5];
    const float* U_l   = (const float*)d_in[6];
    const float* U_r   = (const float*)d_in[7];
    const float* W_f   = (const float*)d_in[8];
    const float* b_f   = (const float*)d_in[9];
    const float* F_ll  = (const float*)d_in[10];
    const float* F_lr  = (const float*)d_in[11];
    const float* F_rl  = (const float*)d_in[12];
    const float* F_rr  = (const float*)d_in[13];

    float* out      = (float*)d_out;
    float* out_h    = out;
    float* out_c    = out + (size_t)HCNT;
    float* out_root = out + 2 * (size_t)HCNT;

    __half *hhb = nullptr, *hlb = nullptr;
    float* cb = nullptr;
    cudaGetSymbolAddress((void**)&hhb, g_hh);
    cudaGetSymbolAddress((void**)&hlb, g_hl);
    cudaGetSymbolAddress((void**)&cb, g_c);

    static int attr_done = 0;
    if (!attr_done) {
        cudaFuncSetAttribute(k_step_mma, cudaFuncAttributeMaxDynamicSharedMemorySize, SMEM_DYN);
        attr_done = 1;
    }

    k_init<<<4096, 256>>>();
    k_pack_wp<<<(WP_TOTAL + 255) / 256, 256>>>(W_iou, b_iou, W_f, b_f);
    k_pack_ub<<<(UB_TOTAL + 255) / 256, 256>>>(U_l, U_r, F_ll, F_lr, F_rl, F_rr);
    k_winner_all<<<dim3(NROWS / 256, NT), 256>>>(td);
    k_compact_all<<<dim3(NROWS / 256, NT), 256>>>(td);
    k_prep_all<<<dim3(NROWS / 256, NT), 256>>>(td, tl, tr);
    k_xgemm_mma<<<dim3(512, 4), 512>>>(X);

    k_step0<<<NROWS / 8, 256>>>(hhb, hlb, cb);
    for (int t = 1; t < NT; t++) {
        k_step_mma<<<dim3(NTL, 512), 512, SMEM_DYN>>>(
            t, hhb, hlb, cb, hhb, hlb, cb);
    }
    k_output<<<4096, 512>>>(hhb, hlb, cb, out_h, out_c);
    k_root<<<NB, 256>>>(td, out_h, out_root);
}